// round 5
// baseline (speedup 1.0000x reference)
#include <cuda_runtime.h>

#define B_    4
#define D_    96
#define N_    512
#define ATTN_ 256

// Scratch for projections (device globals: no allocation in kernel_launch)
__device__ float g_G1[B_ * N_ * ATTN_];   // [b][n][a]
__device__ float g_G2[B_ * N_ * ATTN_];   // [b][m][a]  (bg folded in)

__device__ __forceinline__ float fast_tanh(float x) {
    float y;
    asm("tanh.approx.f32 %0, %1;" : "=f"(y) : "f"(x));
    return y;
}

// ---------------------------------------------------------------------------
// Kernel 1: projections. grid = B*N/16 = 128 blocks, 256 threads (one per a).
// Each block handles 16 n-rows; thread a computes 16 dot products over D=96
// for both Wg1 and Wg2, reusing the weight element across the 16 rows.
// ---------------------------------------------------------------------------
__global__ __launch_bounds__(256) void proj_kernel(
        const float* __restrict__ x,
        const float* __restrict__ Wg1,
        const float* __restrict__ Wg2,
        const float* __restrict__ bg) {
    __shared__ float xs[16 * 96];  // xs[j*96 + d] = x[b, d, n0+j]

    int t  = blockIdx.x;
    int b  = t >> 5;           // 32 tiles of 16 per batch
    int n0 = (t & 31) << 4;

    const float* xb = x + b * D_ * N_;
    for (int idx = threadIdx.x; idx < 16 * 96; idx += 256) {
        int d = idx >> 4, j = idx & 15;
        xs[j * 96 + d] = xb[d * N_ + n0 + j];
    }
    __syncthreads();

    int a = threadIdx.x;
    float acc1[16], acc2[16];
#pragma unroll
    for (int j = 0; j < 16; j++) { acc1[j] = 0.f; acc2[j] = 0.f; }

    const float* w1p = Wg1 + a * D_;
    const float* w2p = Wg2 + a * D_;
#pragma unroll 4
    for (int d = 0; d < D_; d++) {
        float w1 = __ldg(w1p + d);
        float w2 = __ldg(w2p + d);
#pragma unroll
        for (int j = 0; j < 16; j++) {
            float xv = xs[j * 96 + d];
            acc1[j] = fmaf(xv, w1, acc1[j]);
            acc2[j] = fmaf(xv, w2, acc2[j]);
        }
    }

    float bgv = bg[a];
#pragma unroll
    for (int j = 0; j < 16; j++) {
        int row = b * N_ + n0 + j;
        g_G1[row * ATTN_ + a] = acc1[j];
        g_G2[row * ATTN_ + a] = acc2[j] + bgv;
    }
}

// ---------------------------------------------------------------------------
// Kernel 2: fused pairwise tanh + sigmoid + output matmul.
// grid = B * (N/8) = 256 blocks, 256 threads (8 warps).
// warp w <-> n = n0+w ; lane l <-> m = m0+l within a 32-wide m-tile.
// Epilogue: thread (w,l) accumulates out[n0+w][l], [l+32], [l+64].
// ---------------------------------------------------------------------------
#define NT 8
#define MT 32

// float offsets into dynamic smem
#define OFF_G1   0                      // 8*256  = 2048
#define OFF_WS   2048                   // 256
#define OFF_ATT  2304                   // 8*33   = 264
#define OFF_G2   2568                   // 256*33 = 8448
#define OFF_XS   11016                  // 32*97  = 3104
#define SMEM_FLOATS 14120               // 56480 bytes

__global__ __launch_bounds__(256, 2) void attn_kernel(
        const float* __restrict__ x,
        const float* __restrict__ Wa_w,
        const float* __restrict__ Wa_b,
        const float* __restrict__ ba,
        float* __restrict__ out) {
    extern __shared__ float sm[];
    float* G1s   = sm + OFF_G1;    // [n][a]
    float* ws    = sm + OFF_WS;    // [a]
    float* att_s = sm + OFF_ATT;   // [n][33]
    float* G2s   = sm + OFF_G2;    // [a][33] (m in low index, pad 33)
    float* xs    = sm + OFF_XS;    // [m][97] (d in low index, pad 97)

    int blk = blockIdx.x;
    int b   = blk >> 6;            // 64 n-tiles per batch
    int n0  = (blk & 63) << 3;
    int tid = threadIdx.x;
    int w   = tid >> 5, l = tid & 31;

    // Load G1 tile (coalesced over a) + attention weights
    for (int idx = tid; idx < NT * ATTN_; idx += 256)
        G1s[idx] = g_G1[(b * N_ + n0) * ATTN_ + idx];
    ws[tid] = Wa_w[tid];
    float bias = Wa_b[0] + ba[0];

    const float* xb = x + b * D_ * N_;
    float o0 = 0.f, o1 = 0.f, o2 = 0.f;

    for (int mt = 0; mt < N_ / MT; mt++) {
        int m0 = mt * MT;
        __syncthreads();  // previous tile's reads of G2s/xs (and G1s/ws load) done

        // G2 tile, transposed into [a][m] with pad 33 (store: stride-33, CF;
        // read: stride-1 over lanes, CF). Loads coalesced over a.
        const float* g2p = g_G2 + (b * N_ + m0) * ATTN_;
#pragma unroll 8
        for (int k = 0; k < MT; k++)
            G2s[tid * 33 + k] = g2p[k * ATTN_ + tid];

        // x tile [m][d] pad 97: global loads coalesced over m, smem stores CF.
        for (int idx = tid; idx < MT * D_; idx += 256) {
            int m = idx & 31, d = idx >> 5;
            xs[m * 97 + d] = xb[d * N_ + m0 + m];
        }
        __syncthreads();

        // Hot loop: 256 a per (n,m) pair. 4 accumulators for ILP;
        // G1/ws broadcast via LDS.128, G2 lane-parallel conflict-free.
        const float* g1p = G1s + w * ATTN_;
        float a0 = 0.f, a1 = 0.f, a2 = 0.f, a3 = 0.f;
#pragma unroll 4
        for (int a = 0; a < ATTN_; a += 4) {
            float4 g1 = *reinterpret_cast<const float4*>(g1p + a);
            float4 wv = *reinterpret_cast<const float4*>(ws + a);
            float s0 = g1.x + G2s[(a + 0) * 33 + l];
            float s1 = g1.y + G2s[(a + 1) * 33 + l];
            float s2 = g1.z + G2s[(a + 2) * 33 + l];
            float s3 = g1.w + G2s[(a + 3) * 33 + l];
            a0 = fmaf(fast_tanh(s0), wv.x, a0);
            a1 = fmaf(fast_tanh(s1), wv.y, a1);
            a2 = fmaf(fast_tanh(s2), wv.z, a2);
            a3 = fmaf(fast_tanh(s3), wv.w, a3);
        }
        float z   = (a0 + a1) + (a2 + a3) + bias;
        float att = 1.0f / (1.0f + __expf(-z));
        att_s[w * 33 + l] = att;
        __syncthreads();

        // Fused epilogue: out[n][d] += att[n][m] * x[b][d][m] over this m-tile.
        const float* ar = att_s + w * 33;
#pragma unroll 8
        for (int mm = 0; mm < MT; mm++) {
            float av = ar[mm];                      // warp broadcast
            o0 = fmaf(av, xs[mm * 97 + l],      o0);
            o1 = fmaf(av, xs[mm * 97 + l + 32], o1);
            o2 = fmaf(av, xs[mm * 97 + l + 64], o2);
        }
    }

    float* op = out + (b * N_ + n0 + w) * D_;
    op[l]      = o0;
    op[l + 32] = o1;
    op[l + 64] = o2;
}

// ---------------------------------------------------------------------------
extern "C" void kernel_launch(void* const* d_in, const int* in_sizes, int n_in,
                              void* d_out, int out_size) {
    const float* x    = (const float*)d_in[0];
    const float* Wg1  = (const float*)d_in[1];
    const float* Wg2  = (const float*)d_in[2];
    const float* bg   = (const float*)d_in[3];
    const float* Wa_w = (const float*)d_in[4];
    const float* Wa_b = (const float*)d_in[5];
    const float* ba   = (const float*)d_in[6];
    float* out = (float*)d_out;

    proj_kernel<<<(B_ * N_) / 16, 256>>>(x, Wg1, Wg2, bg);

    int smem_bytes = SMEM_FLOATS * (int)sizeof(float);  // 56480
    cudaFuncSetAttribute(attn_kernel,
                         cudaFuncAttributeMaxDynamicSharedMemorySize, smem_bytes);
    attn_kernel<<<B_ * (N_ / NT), 256, smem_bytes>>>(x, Wa_w, Wa_b, ba, out);
}

// round 6
// speedup vs baseline: 1.0023x; 1.0023x over previous
#include <cuda_runtime.h>

#define B_    4
#define D_    96
#define N_    512
#define ATTN_ 256

// Scratch for projections (device globals: no allocation in kernel_launch)
__device__ float g_G1[B_ * N_ * ATTN_];   // [b][n][a]
__device__ float g_G2[B_ * N_ * ATTN_];   // [b][m][a]  (bg folded in)

__device__ __forceinline__ float fast_tanh(float x) {
    float y;
    asm("tanh.approx.f32 %0, %1;" : "=f"(y) : "f"(x));
    return y;
}

// ---------------------------------------------------------------------------
// Kernel 1: projections. grid = B*N/16 = 128 blocks, 256 threads (one per a).
// Each block handles 16 n-rows; thread a computes 16 dot products over D=96
// for both Wg1 and Wg2, reusing the weight element across the 16 rows.
// ---------------------------------------------------------------------------
__global__ __launch_bounds__(256) void proj_kernel(
        const float* __restrict__ x,
        const float* __restrict__ Wg1,
        const float* __restrict__ Wg2,
        const float* __restrict__ bg) {
    __shared__ float xs[16 * 96];  // xs[j*96 + d] = x[b, d, n0+j]

    int t  = blockIdx.x;
    int b  = t >> 5;           // 32 tiles of 16 per batch
    int n0 = (t & 31) << 4;

    const float* xb = x + b * D_ * N_;
    for (int idx = threadIdx.x; idx < 16 * 96; idx += 256) {
        int d = idx >> 4, j = idx & 15;
        xs[j * 96 + d] = xb[d * N_ + n0 + j];
    }
    __syncthreads();

    int a = threadIdx.x;
    float acc1[16], acc2[16];
#pragma unroll
    for (int j = 0; j < 16; j++) { acc1[j] = 0.f; acc2[j] = 0.f; }

    const float* w1p = Wg1 + a * D_;
    const float* w2p = Wg2 + a * D_;
#pragma unroll 4
    for (int d = 0; d < D_; d++) {
        float w1 = __ldg(w1p + d);
        float w2 = __ldg(w2p + d);
#pragma unroll
        for (int j = 0; j < 16; j++) {
            float xv = xs[j * 96 + d];
            acc1[j] = fmaf(xv, w1, acc1[j]);
            acc2[j] = fmaf(xv, w2, acc2[j]);
        }
    }

    float bgv = bg[a];
#pragma unroll
    for (int j = 0; j < 16; j++) {
        int row = b * N_ + n0 + j;
        g_G1[row * ATTN_ + a] = acc1[j];
        g_G2[row * ATTN_ + a] = acc2[j] + bgv;
    }
}

// ---------------------------------------------------------------------------
// Kernel 2: fused pairwise tanh + sigmoid + output matmul.
// grid = B * (N/8) = 256 blocks, 256 threads (8 warps).
// warp w <-> n = n0+w ; lane l <-> m = m0+l within a 32-wide m-tile.
// Epilogue: thread (w,l) accumulates out[n0+w][l], [l+32], [l+64].
// ---------------------------------------------------------------------------
#define NT 8
#define MT 32

// float offsets into dynamic smem
#define OFF_G1   0                      // 8*256  = 2048
#define OFF_WS   2048                   // 256
#define OFF_ATT  2304                   // 8*33   = 264
#define OFF_G2   2568                   // 256*33 = 8448
#define OFF_XS   11016                  // 32*97  = 3104
#define SMEM_FLOATS 14120               // 56480 bytes

__global__ __launch_bounds__(256, 2) void attn_kernel(
        const float* __restrict__ x,
        const float* __restrict__ Wa_w,
        const float* __restrict__ Wa_b,
        const float* __restrict__ ba,
        float* __restrict__ out) {
    extern __shared__ float sm[];
    float* G1s   = sm + OFF_G1;    // [n][a]
    float* ws    = sm + OFF_WS;    // [a]
    float* att_s = sm + OFF_ATT;   // [n][33]
    float* G2s   = sm + OFF_G2;    // [a][33] (m in low index, pad 33)
    float* xs    = sm + OFF_XS;    // [m][97] (d in low index, pad 97)

    int blk = blockIdx.x;
    int b   = blk >> 6;            // 64 n-tiles per batch
    int n0  = (blk & 63) << 3;
    int tid = threadIdx.x;
    int w   = tid >> 5, l = tid & 31;

    // Load G1 tile (coalesced over a) + attention weights
    for (int idx = tid; idx < NT * ATTN_; idx += 256)
        G1s[idx] = g_G1[(b * N_ + n0) * ATTN_ + idx];
    ws[tid] = Wa_w[tid];
    float bias = Wa_b[0] + ba[0];

    const float* xb = x + b * D_ * N_;
    float o0 = 0.f, o1 = 0.f, o2 = 0.f;

    for (int mt = 0; mt < N_ / MT; mt++) {
        int m0 = mt * MT;
        __syncthreads();  // previous tile's reads of G2s/xs (and G1s/ws load) done

        // G2 tile, transposed into [a][m] with pad 33 (store: stride-33, CF;
        // read: stride-1 over lanes, CF). Loads coalesced over a.
        const float* g2p = g_G2 + (b * N_ + m0) * ATTN_;
#pragma unroll 8
        for (int k = 0; k < MT; k++)
            G2s[tid * 33 + k] = g2p[k * ATTN_ + tid];

        // x tile [m][d] pad 97: global loads coalesced over m, smem stores CF.
        for (int idx = tid; idx < MT * D_; idx += 256) {
            int m = idx & 31, d = idx >> 5;
            xs[m * 97 + d] = xb[d * N_ + m0 + m];
        }
        __syncthreads();

        // Hot loop: 256 a per (n,m) pair. 4 accumulators for ILP;
        // G1/ws broadcast via LDS.128, G2 lane-parallel conflict-free.
        const float* g1p = G1s + w * ATTN_;
        float a0 = 0.f, a1 = 0.f, a2 = 0.f, a3 = 0.f;
#pragma unroll 4
        for (int a = 0; a < ATTN_; a += 4) {
            float4 g1 = *reinterpret_cast<const float4*>(g1p + a);
            float4 wv = *reinterpret_cast<const float4*>(ws + a);
            float s0 = g1.x + G2s[(a + 0) * 33 + l];
            float s1 = g1.y + G2s[(a + 1) * 33 + l];
            float s2 = g1.z + G2s[(a + 2) * 33 + l];
            float s3 = g1.w + G2s[(a + 3) * 33 + l];
            a0 = fmaf(fast_tanh(s0), wv.x, a0);
            a1 = fmaf(fast_tanh(s1), wv.y, a1);
            a2 = fmaf(fast_tanh(s2), wv.z, a2);
            a3 = fmaf(fast_tanh(s3), wv.w, a3);
        }
        float z   = (a0 + a1) + (a2 + a3) + bias;
        float att = 1.0f / (1.0f + __expf(-z));
        att_s[w * 33 + l] = att;
        __syncthreads();

        // Fused epilogue: out[n][d] += att[n][m] * x[b][d][m] over this m-tile.
        const float* ar = att_s + w * 33;
#pragma unroll 8
        for (int mm = 0; mm < MT; mm++) {
            float av = ar[mm];                      // warp broadcast
            o0 = fmaf(av, xs[mm * 97 + l],      o0);
            o1 = fmaf(av, xs[mm * 97 + l + 32], o1);
            o2 = fmaf(av, xs[mm * 97 + l + 64], o2);
        }
    }

    float* op = out + (b * N_ + n0 + w) * D_;
    op[l]      = o0;
    op[l + 32] = o1;
    op[l + 64] = o2;
}

// ---------------------------------------------------------------------------
extern "C" void kernel_launch(void* const* d_in, const int* in_sizes, int n_in,
                              void* d_out, int out_size) {
    const float* x    = (const float*)d_in[0];
    const float* Wg1  = (const float*)d_in[1];
    const float* Wg2  = (const float*)d_in[2];
    const float* bg   = (const float*)d_in[3];
    const float* Wa_w = (const float*)d_in[4];
    const float* Wa_b = (const float*)d_in[5];
    const float* ba   = (const float*)d_in[6];
    float* out = (float*)d_out;

    proj_kernel<<<(B_ * N_) / 16, 256>>>(x, Wg1, Wg2, bg);

    int smem_bytes = SMEM_FLOATS * (int)sizeof(float);  // 56480
    cudaFuncSetAttribute(attn_kernel,
                         cudaFuncAttributeMaxDynamicSharedMemorySize, smem_bytes);
    attn_kernel<<<B_ * (N_ / NT), 256, smem_bytes>>>(x, Wa_w, Wa_b, ba, out);
}

// round 7
// speedup vs baseline: 1.0027x; 1.0004x over previous
#include <cuda_runtime.h>

#define B_    4
#define D_    96
#define N_    512
#define ATTN_ 256

// Scratch for projections (device globals: no allocation in kernel_launch)
__device__ float g_G1[B_ * N_ * ATTN_];   // [b][n][a]
__device__ float g_G2[B_ * N_ * ATTN_];   // [b][m][a]  (bg folded in)

__device__ __forceinline__ float fast_tanh(float x) {
    float y;
    asm("tanh.approx.f32 %0, %1;" : "=f"(y) : "f"(x));
    return y;
}

// ---------------------------------------------------------------------------
// Kernel 1: projections. grid = B*N/16 = 128 blocks, 256 threads (one per a).
// Each block handles 16 n-rows; thread a computes 16 dot products over D=96
// for both Wg1 and Wg2, reusing the weight element across the 16 rows.
// ---------------------------------------------------------------------------
__global__ __launch_bounds__(256) void proj_kernel(
        const float* __restrict__ x,
        const float* __restrict__ Wg1,
        const float* __restrict__ Wg2,
        const float* __restrict__ bg) {
    __shared__ float xs[16 * 96];  // xs[j*96 + d] = x[b, d, n0+j]

    int t  = blockIdx.x;
    int b  = t >> 5;           // 32 tiles of 16 per batch
    int n0 = (t & 31) << 4;

    const float* xb = x + b * D_ * N_;
    for (int idx = threadIdx.x; idx < 16 * 96; idx += 256) {
        int d = idx >> 4, j = idx & 15;
        xs[j * 96 + d] = xb[d * N_ + n0 + j];
    }
    __syncthreads();

    int a = threadIdx.x;
    float acc1[16], acc2[16];
#pragma unroll
    for (int j = 0; j < 16; j++) { acc1[j] = 0.f; acc2[j] = 0.f; }

    const float* w1p = Wg1 + a * D_;
    const float* w2p = Wg2 + a * D_;
#pragma unroll 4
    for (int d = 0; d < D_; d++) {
        float w1 = __ldg(w1p + d);
        float w2 = __ldg(w2p + d);
#pragma unroll
        for (int j = 0; j < 16; j++) {
            float xv = xs[j * 96 + d];
            acc1[j] = fmaf(xv, w1, acc1[j]);
            acc2[j] = fmaf(xv, w2, acc2[j]);
        }
    }

    float bgv = bg[a];
#pragma unroll
    for (int j = 0; j < 16; j++) {
        int row = b * N_ + n0 + j;
        g_G1[row * ATTN_ + a] = acc1[j];
        g_G2[row * ATTN_ + a] = acc2[j] + bgv;
    }
}

// ---------------------------------------------------------------------------
// Kernel 2: fused pairwise tanh + sigmoid + output matmul.
// grid = B * (N/8) = 256 blocks, 256 threads (8 warps).
// warp w <-> n = n0+w ; lane l <-> m = m0+l within a 32-wide m-tile.
// Epilogue: thread (w,l) accumulates out[n0+w][l], [l+32], [l+64].
// ---------------------------------------------------------------------------
#define NT 8
#define MT 32

// float offsets into dynamic smem
#define OFF_G1   0                      // 8*256  = 2048
#define OFF_WS   2048                   // 256
#define OFF_ATT  2304                   // 8*33   = 264
#define OFF_G2   2568                   // 256*33 = 8448
#define OFF_XS   11016                  // 32*97  = 3104
#define SMEM_FLOATS 14120               // 56480 bytes

__global__ __launch_bounds__(256, 2) void attn_kernel(
        const float* __restrict__ x,
        const float* __restrict__ Wa_w,
        const float* __restrict__ Wa_b,
        const float* __restrict__ ba,
        float* __restrict__ out) {
    extern __shared__ float sm[];
    float* G1s   = sm + OFF_G1;    // [n][a]
    float* ws    = sm + OFF_WS;    // [a]
    float* att_s = sm + OFF_ATT;   // [n][33]
    float* G2s   = sm + OFF_G2;    // [a][33] (m in low index, pad 33)
    float* xs    = sm + OFF_XS;    // [m][97] (d in low index, pad 97)

    int blk = blockIdx.x;
    int b   = blk >> 6;            // 64 n-tiles per batch
    int n0  = (blk & 63) << 3;
    int tid = threadIdx.x;
    int w   = tid >> 5, l = tid & 31;

    // Load G1 tile (coalesced over a) + attention weights
    for (int idx = tid; idx < NT * ATTN_; idx += 256)
        G1s[idx] = g_G1[(b * N_ + n0) * ATTN_ + idx];
    ws[tid] = Wa_w[tid];
    float bias = Wa_b[0] + ba[0];

    const float* xb = x + b * D_ * N_;
    float o0 = 0.f, o1 = 0.f, o2 = 0.f;

    for (int mt = 0; mt < N_ / MT; mt++) {
        int m0 = mt * MT;
        __syncthreads();  // previous tile's reads of G2s/xs (and G1s/ws load) done

        // G2 tile, transposed into [a][m] with pad 33 (store: stride-33, CF;
        // read: stride-1 over lanes, CF). Loads coalesced over a.
        const float* g2p = g_G2 + (b * N_ + m0) * ATTN_;
#pragma unroll 8
        for (int k = 0; k < MT; k++)
            G2s[tid * 33 + k] = g2p[k * ATTN_ + tid];

        // x tile [m][d] pad 97: global loads coalesced over m, smem stores CF.
        for (int idx = tid; idx < MT * D_; idx += 256) {
            int m = idx & 31, d = idx >> 5;
            xs[m * 97 + d] = xb[d * N_ + m0 + m];
        }
        __syncthreads();

        // Hot loop: 256 a per (n,m) pair. 4 accumulators for ILP;
        // G1/ws broadcast via LDS.128, G2 lane-parallel conflict-free.
        const float* g1p = G1s + w * ATTN_;
        float a0 = 0.f, a1 = 0.f, a2 = 0.f, a3 = 0.f;
#pragma unroll 4
        for (int a = 0; a < ATTN_; a += 4) {
            float4 g1 = *reinterpret_cast<const float4*>(g1p + a);
            float4 wv = *reinterpret_cast<const float4*>(ws + a);
            float s0 = g1.x + G2s[(a + 0) * 33 + l];
            float s1 = g1.y + G2s[(a + 1) * 33 + l];
            float s2 = g1.z + G2s[(a + 2) * 33 + l];
            float s3 = g1.w + G2s[(a + 3) * 33 + l];
            a0 = fmaf(fast_tanh(s0), wv.x, a0);
            a1 = fmaf(fast_tanh(s1), wv.y, a1);
            a2 = fmaf(fast_tanh(s2), wv.z, a2);
            a3 = fmaf(fast_tanh(s3), wv.w, a3);
        }
        float z   = (a0 + a1) + (a2 + a3) + bias;
        float att = 1.0f / (1.0f + __expf(-z));
        att_s[w * 33 + l] = att;
        __syncthreads();

        // Fused epilogue: out[n][d] += att[n][m] * x[b][d][m] over this m-tile.
        const float* ar = att_s + w * 33;
#pragma unroll 8
        for (int mm = 0; mm < MT; mm++) {
            float av = ar[mm];                      // warp broadcast
            o0 = fmaf(av, xs[mm * 97 + l],      o0);
            o1 = fmaf(av, xs[mm * 97 + l + 32], o1);
            o2 = fmaf(av, xs[mm * 97 + l + 64], o2);
        }
    }

    float* op = out + (b * N_ + n0 + w) * D_;
    op[l]      = o0;
    op[l + 32] = o1;
    op[l + 64] = o2;
}

// ---------------------------------------------------------------------------
extern "C" void kernel_launch(void* const* d_in, const int* in_sizes, int n_in,
                              void* d_out, int out_size) {
    const float* x    = (const float*)d_in[0];
    const float* Wg1  = (const float*)d_in[1];
    const float* Wg2  = (const float*)d_in[2];
    const float* bg   = (const float*)d_in[3];
    const float* Wa_w = (const float*)d_in[4];
    const float* Wa_b = (const float*)d_in[5];
    const float* ba   = (const float*)d_in[6];
    float* out = (float*)d_out;

    proj_kernel<<<(B_ * N_) / 16, 256>>>(x, Wg1, Wg2, bg);

    int smem_bytes = SMEM_FLOATS * (int)sizeof(float);  // 56480
    cudaFuncSetAttribute(attn_kernel,
                         cudaFuncAttributeMaxDynamicSharedMemorySize, smem_bytes);
    attn_kernel<<<B_ * (N_ / NT), 256, smem_bytes>>>(x, Wa_w, Wa_b, ba, out);
}